// round 10
// baseline (speedup 1.0000x reference)
#include <cuda_runtime.h>

// TemperatureScaler: piecewise-linear temperature scaling of logits.
// out = T[b]*x + C[b],  b = searchsorted(sorted_thr, x, 'left').
// This round: 256-bit global loads/stores (LDG.E.256 / STG.E.256, sm_100+)
// to halve memory warp-instruction count at identical bytes & MLP.

#define TS_TEMP_MIN 1e-4f
#define TS_MAGIC    12582912.0f   // 2^23 + 2^22: ulp = 1 -> fp add rounds to int

#define TS_LD256(p, r)                                                          \
    asm volatile("ld.global.nc.v8.f32 {%0,%1,%2,%3,%4,%5,%6,%7}, [%8];"         \
        : "=f"((r)[0]), "=f"((r)[1]), "=f"((r)[2]), "=f"((r)[3]),               \
          "=f"((r)[4]), "=f"((r)[5]), "=f"((r)[6]), "=f"((r)[7])                \
        : "l"(p))

#define TS_ST256(p, r)                                                          \
    asm volatile("st.global.v8.f32 [%0], {%1,%2,%3,%4,%5,%6,%7,%8};"            \
        :: "l"(p),                                                              \
           "f"((r)[0]), "f"((r)[1]), "f"((r)[2]), "f"((r)[3]),                  \
           "f"((r)[4]), "f"((r)[5]), "f"((r)[6]), "f"((r)[7])                   \
        : "memory")

__device__ __forceinline__ void ts_build_params(
    const float* __restrict__ temperature, const float* __restrict__ thresholds,
    float* th /*7 sorted*/, float* T /*8*/, float* C /*8*/)
{
    #pragma unroll
    for (int i = 0; i < 7; i++) th[i] = thresholds[i];
    // insertion sort (7 elements) == jnp.sort
    #pragma unroll
    for (int i = 1; i < 7; i++) {
        float v = th[i];
        int j = i - 1;
        while (j >= 0 && th[j] > v) { th[j + 1] = th[j]; j--; }
        th[j + 1] = v;
    }
    #pragma unroll
    for (int i = 0; i < 8; i++) {
        float t = temperature[i];
        T[i] = t < TS_TEMP_MIN ? TS_TEMP_MIN : t;   // clip(lo=1e-4)
    }
    float thrp[8];
    thrp[0] = 0.0f;
    #pragma unroll
    for (int i = 0; i < 7; i++) thrp[i + 1] = th[i];
    // c = cumsum(diff(pad(thr, left0)) * T[:-1])
    float c[8];
    c[0] = 0.0f;
    #pragma unroll
    for (int i = 0; i < 7; i++) {
        float d = __fadd_rn(thrp[i + 1], -thrp[i]);
        c[i + 1] = __fadd_rn(c[i], __fmul_rn(d, T[i]));
    }
    // C[b] = c[b] - T[b]*thrp[b]  (single-FFMA form; ulp-level deviation only)
    #pragma unroll
    for (int i = 0; i < 8; i++) C[i] = __fmaf_rn(-T[i], thrp[i], c[i]);
}

__global__ __launch_bounds__(256, 7) void ts_kernel(
    const float* __restrict__ in, float* __restrict__ out,
    const float* __restrict__ temperature, const float* __restrict__ thresholds,
    long long n8)   // number of float8 (32B) chunks
{
    __shared__ float2 lut[8];   // (T, C)
    __shared__ float sthr[7];   // sorted thresholds (fallback)
    __shared__ float s_inv, s_f;
    __shared__ int   s_uniform;

    if (threadIdx.x == 0) {
        float th[7], T[8], C[8];
        ts_build_params(temperature, thresholds, th, T, C);
        #pragma unroll
        for (int i = 0; i < 8; i++) lut[i] = make_float2(T[i], C[i]);
        #pragma unroll
        for (int i = 0; i < 7; i++) sthr[i] = th[i];

        // near-uniform grid detection: th[i] ~ th0 + i*s with s = span/6
        float span = __fadd_rn(th[6], -th[0]);
        float s    = __fmul_rn(span, 1.0f / 6.0f);
        int uni = (s > 0.0f);
        float tol = 1e-5f * (fabsf(span) + 1.0f);
        #pragma unroll
        for (int i = 0; i < 7; i++) {
            float ideal = __fmaf_rn((float)i, s, th[0]);
            if (fabsf(th[i] - ideal) > tol) uni = 0;
        }
        float inv = uni ? (1.0f / s) : 0.0f;
        s_inv = inv;
        s_f   = __fmaf_rn(-th[0], inv, 0.5f);
        s_uniform = uni;
    }
    __syncthreads();

    const long long base8 = (long long)blockIdx.x * 1024 + threadIdx.x;

    if (s_uniform) {
        const float inv = s_inv, f = s_f;
        auto piece = [&](float x) -> float {
            float y1 = __fmaf_rn(x, inv, f);          // (x-a)/s + 0.5
            y1 = fmaxf(y1, 0.0f);                     // clamp low  (NaN -> 0)
            y1 = fminf(y1, 7.0f);                     // clamp high
            float y  = __fadd_rn(y1, TS_MAGIC);       // round-to-nearest in mantissa
            int b = __float_as_int(y) & 7;            // bin
            float2 L = lut[b];                        // LDS.64, conflict-free
            return __fmaf_rn(L.x, x, L.y);
        };
        if (base8 + 768 < n8) {
            // two halves, each half: MLP-2 of 256-bit loads (64B/thread in flight)
            #pragma unroll
            for (int half = 0; half < 2; half++) {
                const long long o = base8 + half * 512;
                const float* p0 = in + (o << 3);
                const float* p1 = in + ((o + 256) << 3);
                float a[8], b8[8];
                TS_LD256(p0, a);
                TS_LD256(p1, b8);
                float ra[8], rb[8];
                #pragma unroll
                for (int e = 0; e < 8; e++) ra[e] = piece(a[e]);
                #pragma unroll
                for (int e = 0; e < 8; e++) rb[e] = piece(b8[e]);
                TS_ST256(out + (o << 3), ra);
                TS_ST256(out + ((o + 256) << 3), rb);
            }
        } else {
            #pragma unroll
            for (int k = 0; k < 4; k++) {
                long long i8 = base8 + k * 256;
                if (i8 < n8) {
                    const float* p = in + (i8 << 3);
                    float a[8], r[8];
                    TS_LD256(p, a);
                    #pragma unroll
                    for (int e = 0; e < 8; e++) r[e] = piece(a[e]);
                    TS_ST256(out + (i8 << 3), r);
                }
            }
        }
    } else {
        // generic fallback: compare-chain bin search (guarded float8 loop)
        const float t0 = sthr[0], t1 = sthr[1], t2 = sthr[2], t3 = sthr[3],
                    t4 = sthr[4], t5 = sthr[5], t6 = sthr[6];
        auto piece = [&](float x) -> float {
            int b = (x > t0);
            b += (x > t1); b += (x > t2); b += (x > t3);
            b += (x > t4); b += (x > t5); b += (x > t6);
            float2 L = lut[b];
            return __fmaf_rn(L.x, x, L.y);
        };
        #pragma unroll
        for (int k = 0; k < 4; k++) {
            long long i8 = base8 + k * 256;
            if (i8 < n8) {
                const float* p = in + (i8 << 3);
                float a[8], r[8];
                TS_LD256(p, a);
                #pragma unroll
                for (int e = 0; e < 8; e++) r[e] = piece(a[e]);
                TS_ST256(out + (i8 << 3), r);
            }
        }
    }
}

// Scalar tail for out_size % 8 != 0 (not hit for B=64, V=128000)
__global__ void ts_tail_kernel(
    const float* __restrict__ in, float* __restrict__ out,
    const float* __restrict__ temperature, const float* __restrict__ thresholds,
    long long start, long long n)
{
    float th[7], T[8], C[8];
    ts_build_params(temperature, thresholds, th, T, C);
    for (long long i = start + threadIdx.x; i < n; i += blockDim.x) {
        float x = in[i];
        int b = 0;
        #pragma unroll
        for (int j = 0; j < 7; j++) b += (x > th[j]);
        out[i] = __fmaf_rn(T[b], x, C[b]);
    }
}

extern "C" void kernel_launch(void* const* d_in, const int* in_sizes, int n_in,
                              void* d_out, int out_size) {
    const float* logits      = (const float*)d_in[0];
    const float* temperature = (const float*)d_in[1];
    const float* thresholds  = (const float*)d_in[2];
    float* out = (float*)d_out;

    long long n  = out_size;        // 8,192,000 floats
    long long n8 = n >> 3;          // 1,024,000 float8 (32B) chunks

    int grid = (int)((n8 + 1023) / 1024);   // 4 float8/thread -> 1000 blocks
    if (grid < 1) grid = 1;

    ts_kernel<<<grid, 256>>>(logits, out, temperature, thresholds, n8);

    long long rem = n - (n8 << 3);
    if (rem > 0) {
        ts_tail_kernel<<<1, 256>>>(logits, out, temperature, thresholds, n8 << 3, n);
    }
}

// round 11
// speedup vs baseline: 1.3608x; 1.3608x over previous
#include <cuda_runtime.h>

// TemperatureScaler: piecewise-linear temperature scaling of logits.
// out = T[b]*x + C[b],  b = searchsorted(sorted_thr, x, 'left').
// Hot path: magic-number binning (fma/alu pipes only) + front-batched
// 8x LDG.128 per thread (MLP_p1=8) with compute/store draining behind.

#define TS_TEMP_MIN 1e-4f
#define TS_MAGIC    12582912.0f   // 2^23 + 2^22: fp add rounds to int in mantissa

__device__ __forceinline__ void ts_build_params(
    const float* __restrict__ temperature, const float* __restrict__ thresholds,
    float* th /*7 sorted*/, float* T /*8*/, float* C /*8*/)
{
    #pragma unroll
    for (int i = 0; i < 7; i++) th[i] = thresholds[i];
    // insertion sort (7 elements) == jnp.sort
    #pragma unroll
    for (int i = 1; i < 7; i++) {
        float v = th[i];
        int j = i - 1;
        while (j >= 0 && th[j] > v) { th[j + 1] = th[j]; j--; }
        th[j + 1] = v;
    }
    #pragma unroll
    for (int i = 0; i < 8; i++) {
        float t = temperature[i];
        T[i] = t < TS_TEMP_MIN ? TS_TEMP_MIN : t;   // clip(lo=1e-4)
    }
    float thrp[8];
    thrp[0] = 0.0f;
    #pragma unroll
    for (int i = 0; i < 7; i++) thrp[i + 1] = th[i];
    // c = cumsum(diff(pad(thr, left0)) * T[:-1])
    float c[8];
    c[0] = 0.0f;
    #pragma unroll
    for (int i = 0; i < 7; i++) {
        float d = __fadd_rn(thrp[i + 1], -thrp[i]);
        c[i + 1] = __fadd_rn(c[i], __fmul_rn(d, T[i]));
    }
    // C[b] = c[b] - T[b]*thrp[b]  (single-FFMA form; ulp-level deviation only)
    #pragma unroll
    for (int i = 0; i < 8; i++) C[i] = __fmaf_rn(-T[i], thrp[i], c[i]);
}

__global__ __launch_bounds__(256, 5) void ts_kernel(
    const float4* __restrict__ in, float4* __restrict__ out,
    const float* __restrict__ temperature, const float* __restrict__ thresholds,
    int n4)
{
    __shared__ float2 lut[8];   // (T, C)
    __shared__ float sthr[7];   // sorted thresholds (fallback)
    __shared__ float s_inv, s_f;
    __shared__ int   s_uniform;

    if (threadIdx.x == 0) {
        float th[7], T[8], C[8];
        ts_build_params(temperature, thresholds, th, T, C);
        #pragma unroll
        for (int i = 0; i < 8; i++) lut[i] = make_float2(T[i], C[i]);
        #pragma unroll
        for (int i = 0; i < 7; i++) sthr[i] = th[i];

        // near-uniform grid detection: th[i] ~ th0 + i*s with s = span/6
        float span = __fadd_rn(th[6], -th[0]);
        float s    = __fmul_rn(span, 1.0f / 6.0f);
        int uni = (s > 0.0f);
        float tol = 1e-5f * (fabsf(span) + 1.0f);
        #pragma unroll
        for (int i = 0; i < 7; i++) {
            float ideal = __fmaf_rn((float)i, s, th[0]);
            if (fabsf(th[i] - ideal) > tol) uni = 0;
        }
        float inv = uni ? (1.0f / s) : 0.0f;
        s_inv = inv;
        s_f   = __fmaf_rn(-th[0], inv, 0.5f);
        s_uniform = uni;
    }
    __syncthreads();

    const int base = blockIdx.x * 2048 + threadIdx.x;

    if (s_uniform) {
        const float inv = s_inv, f = s_f;
        auto piece = [&](float x) -> float {
            float y1 = __fmaf_rn(x, inv, f);          // (x-a)/s + 0.5
            y1 = fmaxf(y1, 0.0f);                     // clamp low (NaN -> 0)
            y1 = fminf(y1, 7.0f);                     // clamp high
            float y  = __fadd_rn(y1, TS_MAGIC);       // round-to-nearest int
            int b = __float_as_int(y) & 7;            // bin
            float2 L = lut[b];                        // LDS.64, conflict-free
            return __fmaf_rn(L.x, x, L.y);
        };
        if (base + 1792 < n4) {
            // front-batch ALL 8 loads: 8 independent LDG.128 in flight
            float4 v0 = in[base];
            float4 v1 = in[base + 256];
            float4 v2 = in[base + 512];
            float4 v3 = in[base + 768];
            float4 v4 = in[base + 1024];
            float4 v5 = in[base + 1280];
            float4 v6 = in[base + 1536];
            float4 v7 = in[base + 1792];
            // compute+store drain in arrival order; stores overlap later loads
            v0.x = piece(v0.x); v0.y = piece(v0.y); v0.z = piece(v0.z); v0.w = piece(v0.w);
            out[base]        = v0;
            v1.x = piece(v1.x); v1.y = piece(v1.y); v1.z = piece(v1.z); v1.w = piece(v1.w);
            out[base + 256]  = v1;
            v2.x = piece(v2.x); v2.y = piece(v2.y); v2.z = piece(v2.z); v2.w = piece(v2.w);
            out[base + 512]  = v2;
            v3.x = piece(v3.x); v3.y = piece(v3.y); v3.z = piece(v3.z); v3.w = piece(v3.w);
            out[base + 768]  = v3;
            v4.x = piece(v4.x); v4.y = piece(v4.y); v4.z = piece(v4.z); v4.w = piece(v4.w);
            out[base + 1024] = v4;
            v5.x = piece(v5.x); v5.y = piece(v5.y); v5.z = piece(v5.z); v5.w = piece(v5.w);
            out[base + 1280] = v5;
            v6.x = piece(v6.x); v6.y = piece(v6.y); v6.z = piece(v6.z); v6.w = piece(v6.w);
            out[base + 1536] = v6;
            v7.x = piece(v7.x); v7.y = piece(v7.y); v7.z = piece(v7.z); v7.w = piece(v7.w);
            out[base + 1792] = v7;
        } else {
            #pragma unroll
            for (int k = 0; k < 8; k++) {
                int i = base + k * 256;
                if (i < n4) {
                    float4 v = in[i];
                    float4 r;
                    r.x = piece(v.x); r.y = piece(v.y); r.z = piece(v.z); r.w = piece(v.w);
                    out[i] = r;
                }
            }
        }
    } else {
        // generic fallback: compare-chain bin search
        const float t0 = sthr[0], t1 = sthr[1], t2 = sthr[2], t3 = sthr[3],
                    t4 = sthr[4], t5 = sthr[5], t6 = sthr[6];
        auto piece = [&](float x) -> float {
            int b = (x > t0);
            b += (x > t1); b += (x > t2); b += (x > t3);
            b += (x > t4); b += (x > t5); b += (x > t6);
            float2 L = lut[b];
            return __fmaf_rn(L.x, x, L.y);
        };
        #pragma unroll
        for (int k = 0; k < 8; k++) {
            int i = base + k * 256;
            if (i < n4) {
                float4 v = in[i];
                float4 r;
                r.x = piece(v.x); r.y = piece(v.y); r.z = piece(v.z); r.w = piece(v.w);
                out[i] = r;
            }
        }
    }
}

// Scalar tail for out_size % 4 != 0 (not hit for B=64, V=128000)
__global__ void ts_tail_kernel(
    const float* __restrict__ in, float* __restrict__ out,
    const float* __restrict__ temperature, const float* __restrict__ thresholds,
    int start, int n)
{
    float th[7], T[8], C[8];
    ts_build_params(temperature, thresholds, th, T, C);
    for (int i = start + threadIdx.x; i < n; i += blockDim.x) {
        float x = in[i];
        int b = 0;
        #pragma unroll
        for (int j = 0; j < 7; j++) b += (x > th[j]);
        out[i] = __fmaf_rn(T[b], x, C[b]);
    }
}

extern "C" void kernel_launch(void* const* d_in, const int* in_sizes, int n_in,
                              void* d_out, int out_size) {
    const float* logits      = (const float*)d_in[0];
    const float* temperature = (const float*)d_in[1];
    const float* thresholds  = (const float*)d_in[2];
    float* out = (float*)d_out;

    int n  = out_size;           // 8,192,000
    int n4 = n >> 2;             // 2,048,000 float4s

    int grid = (n4 + 2047) / 2048;   // 8 float4 per thread -> 1000 blocks
    if (grid < 1) grid = 1;

    ts_kernel<<<grid, 256>>>((const float4*)logits, (float4*)out,
                             temperature, thresholds, n4);

    int rem = n - (n4 << 2);
    if (rem > 0) {
        ts_tail_kernel<<<1, 256>>>(logits, out, temperature, thresholds, n4 << 2, n);
    }
}